// round 1
// baseline (speedup 1.0000x reference)
#include <cuda_runtime.h>
#include <cstdint>

typedef unsigned long long u64;

// ---------- f32x2 packed-math helpers (sm_100+ FFMA2 path) ----------
__device__ __forceinline__ u64 pk2(float lo, float hi) {
    u64 r; asm("mov.b64 %0, {%1,%2};" : "=l"(r) : "f"(lo), "f"(hi)); return r;
}
__device__ __forceinline__ u64 dup2(float v) { return pk2(v, v); }
__device__ __forceinline__ void unpk2(u64 v, float &lo, float &hi) {
    asm("mov.b64 {%0,%1}, %2;" : "=f"(lo), "=f"(hi) : "l"(v));
}
__device__ __forceinline__ void fma2(u64 &d, u64 a, u64 b) {
    asm("fma.rn.f32x2 %0, %1, %2, %0;" : "+l"(d) : "l"(a), "l"(b));
}

// ---------- smem layout (floats) ----------
// xT   [128][66]  : x transposed (feature-major), pad 66 (even -> 8B-aligned float2 rows)
// WS   region 16704 floats:
//        during QKV GEMM : ws[128][129]   (W_in e-tile, natural layout, pad 129)
//        after attention : wo[64][129] (first 8256) + ctxT[128][66] (at +8256)
// kT   [128][66]  : K transposed
// vT   [128][66]  : V transposed
// QA   [64][128]  : Q during attention, then attended
// POOL [4][128] + AW[64]
#define OXT   0
#define OWS   8448
#define OCT   (OWS + 8256)
#define OKT   (OWS + 16704)
#define OVT   (OKT + 8448)
#define OQA   (OVT + 8448)
#define OPOOL (OQA + 8192)
#define OAW   (OPOOL + 512)
#define SMEM_FLOATS (OAW + 64)
#define SMEM_BYTES  (SMEM_FLOATS * 4)   // 203,264 B

__global__ void __launch_bounds__(256, 1)
feat_kernel(const float* __restrict__ xg_all,
            const float* __restrict__ W_in,  const float* __restrict__ b_in,
            const float* __restrict__ W_out, const float* __restrict__ b_out,
            const float* __restrict__ W_pool, const float* __restrict__ b_pool,
            float* __restrict__ out)
{
    extern __shared__ float sm[];
    const int tid  = threadIdx.x;
    const int lane = tid & 31;
    const int warp = tid >> 5;
    const int bm   = blockIdx.x;
    const float* xg = xg_all + (size_t)bm * (64 * 128);

    // ---------------- phase 0: load x, transposed xT[d][l] ----------------
    #pragma unroll
    for (int r = 0; r < 8; ++r) {
        int idx = tid + 256 * r;              // 2048 float4 total
        int l = idx >> 5, k4 = idx & 31;
        float4 v = *reinterpret_cast<const float4*>(xg + l * 128 + k4 * 4);
        int base = OXT + (k4 * 4) * 66 + l;
        sm[base]       = v.x;
        sm[base + 66]  = v.y;
        sm[base + 132] = v.z;
        sm[base + 198] = v.w;
    }

    // ---------------- phase 1: QKV = x @ W_in^T + b_in ----------------
    // 3 e-tiles of 128. C-tile 64l x 128e over 256 threads: microtile 8l x 4e,
    // l-paired f32x2 accumulators (16 FFMA2 / 8 LDS-equiv per kk).
    {
        const int tx = tid & 31;   // e lane: e = tx + 32j
        const int ty = tid >> 5;   // l block: l0 = 8*ty  (== warp -> broadcast A reads)
        const int l0 = ty * 8;
        for (int t = 0; t < 3; ++t) {
            __syncthreads();
            // load W_in rows [128t, 128t+128) -> ws[e][129]
            #pragma unroll
            for (int r = 0; r < 16; ++r) {
                int idx = tid + 256 * r;      // 4096 float4
                int e = idx >> 5, k4 = idx & 31;
                float4 w4 = *reinterpret_cast<const float4*>(
                    W_in + (size_t)(128 * t + e) * 128 + k4 * 4);
                int wb = OWS + e * 129 + k4 * 4;
                sm[wb] = w4.x; sm[wb + 1] = w4.y; sm[wb + 2] = w4.z; sm[wb + 3] = w4.w;
            }
            __syncthreads();

            u64 acc[16];
            #pragma unroll
            for (int j = 0; j < 4; ++j) {
                u64 bb = dup2(b_in[128 * t + tx + 32 * j]);
                #pragma unroll
                for (int lp = 0; lp < 4; ++lp) acc[lp * 4 + j] = bb;
            }
            #pragma unroll 4
            for (int kk = 0; kk < 128; ++kk) {
                u64 a[4];
                #pragma unroll
                for (int lp = 0; lp < 4; ++lp)
                    a[lp] = *reinterpret_cast<const u64*>(&sm[OXT + kk * 66 + l0 + 2 * lp]);
                #pragma unroll
                for (int j = 0; j < 4; ++j) {
                    u64 b2 = dup2(sm[OWS + (tx + 32 * j) * 129 + kk]);
                    #pragma unroll
                    for (int lp = 0; lp < 4; ++lp) fma2(acc[lp * 4 + j], a[lp], b2);
                }
            }
            // writeback: Q normal [64][128], K/V transposed [e][66]
            #pragma unroll
            for (int j = 0; j < 4; ++j) {
                int eg = tx + 32 * j;
                #pragma unroll
                for (int lp = 0; lp < 4; ++lp) {
                    float v0, v1; unpk2(acc[lp * 4 + j], v0, v1);
                    int l = l0 + 2 * lp;
                    if (t == 0) {
                        sm[OQA + l * 128 + eg]       = v0;
                        sm[OQA + (l + 1) * 128 + eg] = v1;
                    } else if (t == 1) {
                        sm[OKT + eg * 66 + l]     = v0;
                        sm[OKT + eg * 66 + l + 1] = v1;
                    } else {
                        sm[OVT + eg * 66 + l]     = v0;
                        sm[OVT + eg * 66 + l + 1] = v1;
                    }
                }
            }
        }
    }
    __syncthreads();

    // ---------------- phase 2: attention (warp per (h,l) task) ----------------
    // lane owns key pair (2*lane, 2*lane+1) for scores; lane owns dim d=lane for ctx.
    {
        for (int i = 0; i < 32; ++i) {
            int task = warp * 32 + i;
            int h = task >> 6, l = task & 63;
            int hb = h * 32;
            u64 s2 = 0;   // packed (0,0)
            #pragma unroll
            for (int kk = 0; kk < 32; ++kk) {
                u64 q2 = dup2(sm[OQA + l * 128 + hb + kk]);
                u64 kv = *reinterpret_cast<const u64*>(&sm[OKT + (hb + kk) * 66 + 2 * lane]);
                fma2(s2, q2, kv);
            }
            float sa, sb; unpk2(s2, sa, sb);
            sa *= 0.17677669529663687f;   // 1/sqrt(32)
            sb *= 0.17677669529663687f;
            float mx = fmaxf(sa, sb);
            #pragma unroll
            for (int o = 16; o > 0; o >>= 1)
                mx = fmaxf(mx, __shfl_xor_sync(0xffffffffu, mx, o));
            float ea = __expf(sa - mx), eb = __expf(sb - mx);
            float s = ea + eb;
            #pragma unroll
            for (int o = 16; o > 0; o >>= 1)
                s += __shfl_xor_sync(0xffffffffu, s, o);
            float inv = 1.0f / s;
            float pa = ea * inv, pb = eb * inv;
            // ctx[l, hb+lane] = sum_m p[m] * v[m, hb+lane]
            u64 c2 = 0;
            #pragma unroll 8
            for (int m2 = 0; m2 < 32; ++m2) {
                float ba = __shfl_sync(0xffffffffu, pa, m2);
                float bb = __shfl_sync(0xffffffffu, pb, m2);
                u64 p2 = pk2(ba, bb);
                u64 vv = *reinterpret_cast<const u64*>(&sm[OVT + (hb + lane) * 66 + 2 * m2]);
                fma2(c2, p2, vv);
            }
            float c0, c1; unpk2(c2, c0, c1);
            sm[OCT + (hb + lane) * 66 + l] = c0 + c1;
        }
    }
    __syncthreads();

    // ---------------- phase 3: attended = ctx @ W_out^T + b_out -> QA ----------------
    // 2 e-tiles of 64. microtile 4l x 4e per thread.
    {
        const int txp = tid & 15;   // e = txp + 16j
        const int typ = tid >> 4;   // l0 = 4*typ
        const int l0  = typ * 4;
        for (int t = 0; t < 2; ++t) {
            #pragma unroll
            for (int r = 0; r < 8; ++r) {
                int idx = tid + 256 * r;     // 2048 float4
                int e = idx >> 5, k4 = idx & 31;
                float4 w4 = *reinterpret_cast<const float4*>(
                    W_out + (size_t)(64 * t + e) * 128 + k4 * 4);
                int wb = OWS + e * 129 + k4 * 4;
                sm[wb] = w4.x; sm[wb + 1] = w4.y; sm[wb + 2] = w4.z; sm[wb + 3] = w4.w;
            }
            __syncthreads();

            u64 acc[8];
            #pragma unroll
            for (int j = 0; j < 4; ++j) {
                u64 bb = dup2(b_out[64 * t + txp + 16 * j]);
                acc[j] = bb; acc[4 + j] = bb;
            }
            #pragma unroll 4
            for (int kk = 0; kk < 128; ++kk) {
                u64 a0 = *reinterpret_cast<const u64*>(&sm[OCT + kk * 66 + l0]);
                u64 a1 = *reinterpret_cast<const u64*>(&sm[OCT + kk * 66 + l0 + 2]);
                #pragma unroll
                for (int j = 0; j < 4; ++j) {
                    u64 b2 = dup2(sm[OWS + (txp + 16 * j) * 129 + kk]);
                    fma2(acc[j],     a0, b2);
                    fma2(acc[4 + j], a1, b2);
                }
            }
            __syncthreads();   // everyone done reading WS tile before next overwrite
            #pragma unroll
            for (int j = 0; j < 4; ++j) {
                int eg = 64 * t + txp + 16 * j;
                float v0, v1;
                unpk2(acc[j], v0, v1);
                sm[OQA + l0 * 128 + eg]       = v0;
                sm[OQA + (l0 + 1) * 128 + eg] = v1;
                unpk2(acc[4 + j], v0, v1);
                sm[OQA + (l0 + 2) * 128 + eg] = v0;
                sm[OQA + (l0 + 3) * 128 + eg] = v1;
            }
        }
    }
    __syncthreads();

    // ---------------- phase 4: pooling + projections ----------------
    // 4a: aw logits[l] = dot(attended[l], x[l])
    #pragma unroll
    for (int i = 0; i < 8; ++i) {
        int l = warp * 8 + i;
        float p = 0.f;
        #pragma unroll
        for (int c = 0; c < 4; ++c) {
            int d = lane + 32 * c;
            p = fmaf(sm[OQA + l * 128 + d], sm[OXT + d * 66 + l], p);
        }
        #pragma unroll
        for (int o = 16; o > 0; o >>= 1) p += __shfl_xor_sync(0xffffffffu, p, o);
        if (lane == 0) sm[OAW + l] = p;
    }
    __syncthreads();
    // 4b: softmax over l (warp 0)
    if (warp == 0) {
        float va = sm[OAW + lane], vb = sm[OAW + lane + 32];
        float mx = fmaxf(va, vb);
        #pragma unroll
        for (int o = 16; o > 0; o >>= 1)
            mx = fmaxf(mx, __shfl_xor_sync(0xffffffffu, mx, o));
        float ea = __expf(va - mx), eb = __expf(vb - mx);
        float s = ea + eb;
        #pragma unroll
        for (int o = 16; o > 0; o >>= 1) s += __shfl_xor_sync(0xffffffffu, s, o);
        float inv = 1.0f / s;
        sm[OAW + lane]      = ea * inv;
        sm[OAW + lane + 32] = eb * inv;
    }
    __syncthreads();
    // 4c: per-dim stats over l
    if (tid < 128) {
        int d = tid;
        float wacc = 0.f, s = 0.f, s2 = 0.f, mx = -3.4e38f;
        #pragma unroll 8
        for (int l = 0; l < 64; ++l) {
            float a = sm[OQA + l * 128 + d];
            wacc = fmaf(sm[OAW + l], a, wacc);
            s += a;
            s2 = fmaf(a, a, s2);
            mx = fmaxf(mx, a);
        }
        float mean = s * (1.0f / 64.0f);
        float var  = (s2 - s * mean) * (1.0f / 63.0f);   // unbiased (ddof=1)
        sm[OPOOL + d]       = wacc;
        sm[OPOOL + 128 + d] = mx;
        sm[OPOOL + 256 + d] = mean;
        sm[OPOOL + 384 + d] = sqrtf(fmaxf(var, 0.0f));
    }
    __syncthreads();
    // 4d: 4 small projections -> out[bm, 64]
    {
        int p  = warp >> 1;
        int f0 = (warp & 1) * 8;
        #pragma unroll
        for (int fi = 0; fi < 8; ++fi) {
            int o = p * 16 + f0 + fi;
            float acc = 0.f;
            #pragma unroll
            for (int c = 0; c < 4; ++c) {
                int d = lane + 32 * c;
                acc = fmaf(sm[OPOOL + p * 128 + d], W_pool[(size_t)o * 128 + d], acc);
            }
            #pragma unroll
            for (int off = 16; off > 0; off >>= 1)
                acc += __shfl_xor_sync(0xffffffffu, acc, off);
            if (lane == 0) out[(size_t)bm * 64 + o] = acc + b_pool[o];
        }
    }
}

extern "C" void kernel_launch(void* const* d_in, const int* in_sizes, int n_in,
                              void* d_out, int out_size)
{
    const float* x      = (const float*)d_in[0];
    // d_in[1] = batch_indices (int64) — equal-length segments, unused
    const float* W_in   = (const float*)d_in[2];
    const float* b_in   = (const float*)d_in[3];
    const float* W_out  = (const float*)d_in[4];
    const float* b_out  = (const float*)d_in[5];
    const float* W_pool = (const float*)d_in[6];
    const float* b_pool = (const float*)d_in[7];
    float* out = (float*)d_out;

    int nmol = in_sizes[0] / (64 * 128);   // 8192

    cudaFuncSetAttribute(feat_kernel,
                         cudaFuncAttributeMaxDynamicSharedMemorySize, SMEM_BYTES);
    feat_kernel<<<nmol, 256, SMEM_BYTES>>>(x, W_in, b_in, W_out, b_out,
                                           W_pool, b_pool, out);
}

// round 6
// speedup vs baseline: 1.0858x; 1.0858x over previous
#include <cuda_runtime.h>
#include <cuda_bf16.h>
#include <cstdint>

typedef unsigned long long u64;
typedef unsigned int u32;

// ---------- helpers ----------
__device__ __forceinline__ u64 pk2(float lo, float hi) {
    u64 r; asm("mov.b64 %0, {%1,%2};" : "=l"(r) : "f"(lo), "f"(hi)); return r;
}
__device__ __forceinline__ u64 dup2(float v) { return pk2(v, v); }
__device__ __forceinline__ void unpk2(u64 v, float &lo, float &hi) {
    asm("mov.b64 {%0,%1}, %2;" : "=f"(lo), "=f"(hi) : "l"(v));
}
__device__ __forceinline__ void fma2(u64 &d, u64 a, u64 b) {
    asm("fma.rn.f32x2 %0, %1, %2, %0;" : "+l"(d) : "l"(a), "l"(b));
}
// pack bf16(lo),bf16(hi) -> u32 (lo in low 16 bits)
__device__ __forceinline__ u32 bf2(float lo, float hi){
    u32 r; asm("cvt.rn.bf16x2.f32 %0, %1, %2;" : "=r"(r) : "f"(hi), "f"(lo)); return r;
}
__device__ __forceinline__ void mma16816(float* d, const u32* a, const u32* b){
    asm volatile("mma.sync.aligned.m16n8k16.row.col.f32.bf16.bf16.f32 "
        "{%0,%1,%2,%3}, {%4,%5,%6,%7}, {%8,%9}, {%0,%1,%2,%3};"
        : "+f"(d[0]),"+f"(d[1]),"+f"(d[2]),"+f"(d[3])
        : "r"(a[0]),"r"(a[1]),"r"(a[2]),"r"(a[3]), "r"(b[0]),"r"(b[1]));
}

// ---------- prepped W_in: [384 rows][136] bf16 hi/lo ----------
__device__ __align__(16) __nv_bfloat16 g_wh[384 * 136];
__device__ __align__(16) __nv_bfloat16 g_wl[384 * 136];

__global__ void prep_kernel(const float* __restrict__ W_in){
    int idx = blockIdx.x * 256 + threadIdx.x;      // 49152
    int r = idx >> 7, c = idx & 127;
    float v = W_in[r * 128 + c];
    __nv_bfloat16 h = __float2bfloat16(v);
    float hf = __bfloat162float(h);
    g_wh[r * 136 + c] = h;
    g_wl[r * 136 + c] = __float2bfloat16(v - hf);
}

// ---------- smem layout (floats) — EXACT R1 ----------
#define OXT   0
#define OWS   8448
#define OCT   (OWS + 8256)
#define OKT   (OWS + 16704)
#define OVT   (OKT + 8448)
#define OQA   (OVT + 8448)
#define OPOOL (OQA + 8192)
#define OAW   (OPOOL + 512)
#define SMEM_FLOATS (OAW + 64)
#define SMEM_BYTES  (SMEM_FLOATS * 4)   // 203,264 B
#define WLO 4352

__global__ void __launch_bounds__(256, 1)
feat_kernel(const float* __restrict__ xg_all,
            const float* __restrict__ b_in,
            const float* __restrict__ W_out, const float* __restrict__ b_out,
            const float* __restrict__ W_pool, const float* __restrict__ b_pool,
            float* __restrict__ out)
{
    extern __shared__ float sm[];
    u32* smw = (u32*)sm;
    const int tid  = threadIdx.x;
    const int lane = tid & 31;
    const int warp = tid >> 5;
    const int bm   = blockIdx.x;
    const float* xg = xg_all + (size_t)bm * (64 * 128);

    // ---------------- phase 0: load x, transposed xT[d][l] (R1 verbatim) ----------------
    #pragma unroll
    for (int r = 0; r < 8; ++r) {
        int idx = tid + 256 * r;              // 2048 float4 total
        int l = idx >> 5, k4 = idx & 31;
        float4 v = *reinterpret_cast<const float4*>(xg + l * 128 + k4 * 4);
        int base = OXT + (k4 * 4) * 66 + l;
        sm[base]       = v.x;
        sm[base + 66]  = v.y;
        sm[base + 132] = v.z;
        sm[base + 198] = v.w;
    }
    __syncthreads();

    // ---------------- phase 1 (NEW): QKV via mma bf16 hi/lo ----------------
    // warp stripe: rows (warp&3)*16 .. +15 ; col half: (warp>>2)*32 within each 64-col stage
    u32 Ah[32], Al[32];
    {
        const int s16 = (warp & 3) * 16;
        #pragma unroll
        for (int ks = 0; ks < 8; ++ks){
            #pragma unroll
            for (int q = 0; q < 4; ++q){
                int rr = s16 + (lane >> 2) + (q & 1) * 8;
                int k  = ks * 16 + 2 * (lane & 3) + (q >> 1) * 8;
                float f0 = sm[OXT + k * 66 + rr];
                float f1 = sm[OXT + (k + 1) * 66 + rr];
                u32 h = bf2(f0, f1);
                Ah[4 * ks + q] = h;
                float xr = __uint_as_float(h << 16);
                float yr = __uint_as_float(h & 0xffff0000u);
                Al[4 * ks + q] = bf2(f0 - xr, f1 - yr);
            }
        }
    }
    for (int si = 0; si < 6; ++si){
        __syncthreads();
        const uint4* srch = (const uint4*)(g_wh + (size_t)si * 8704);
        const uint4* srcl = (const uint4*)(g_wl + (size_t)si * 8704);
        uint4* dsth = (uint4*)&smw[OWS];
        uint4* dstl = (uint4*)&smw[OWS + WLO];
        for (int i = tid; i < 1088; i += 256){ dsth[i] = srch[i]; dstl[i] = srcl[i]; }
        __syncthreads();

        const int nh = warp >> 2;
        for (int j = 0; j < 4; ++j){
            float acc[4] = {0.f, 0.f, 0.f, 0.f};
            int bw = OWS + (nh * 32 + 8 * j + (lane >> 2)) * 68 + (lane & 3);
            #pragma unroll
            for (int p = 0; p < 4; ++p){
                u32 Bh[4], Bl[4];
                int bp = bw + p * 16;
                Bh[0] = smw[bp];      Bh[1] = smw[bp + 4];
                Bh[2] = smw[bp + 8];  Bh[3] = smw[bp + 12];
                Bl[0] = smw[bp + WLO];      Bl[1] = smw[bp + 4 + WLO];
                Bl[2] = smw[bp + 8 + WLO];  Bl[3] = smw[bp + 12 + WLO];
                mma16816(acc, &Ah[8*p],     &Bh[0]);
                mma16816(acc, &Ah[8*p],     &Bl[0]);
                mma16816(acc, &Al[8*p],     &Bh[0]);
                mma16816(acc, &Ah[8*p + 4], &Bh[2]);
                mma16816(acc, &Ah[8*p + 4], &Bl[2]);
                mma16816(acc, &Al[8*p + 4], &Bh[2]);
            }
            int e0 = si * 64 + nh * 32 + 8 * j + 2 * (lane & 3);
            int r0 = (warp & 3) * 16 + (lane >> 2);
            float v0 = acc[0] + b_in[e0];
            float v1 = acc[1] + b_in[e0 + 1];
            float v2 = acc[2] + b_in[e0];
            float v3 = acc[3] + b_in[e0 + 1];
            if (e0 < 128){
                sm[OQA + r0 * 128 + e0]           = v0;
                sm[OQA + r0 * 128 + e0 + 1]       = v1;
                sm[OQA + (r0 + 8) * 128 + e0]     = v2;
                sm[OQA + (r0 + 8) * 128 + e0 + 1] = v3;
            } else if (e0 < 256){
                int ek = e0 - 128;
                sm[OKT + ek * 66 + r0]           = v0;
                sm[OKT + (ek + 1) * 66 + r0]     = v1;
                sm[OKT + ek * 66 + r0 + 8]       = v2;
                sm[OKT + (ek + 1) * 66 + r0 + 8] = v3;
            } else {
                int ev = e0 - 256;
                sm[OVT + ev * 66 + r0]           = v0;
                sm[OVT + (ev + 1) * 66 + r0]     = v1;
                sm[OVT + ev * 66 + r0 + 8]       = v2;
                sm[OVT + (ev + 1) * 66 + r0 + 8] = v3;
            }
        }
    }
    __syncthreads();

    // ---------------- phase 2: attention (R1 verbatim) ----------------
    {
        for (int i = 0; i < 32; ++i) {
            int task = warp * 32 + i;
            int h = task >> 6, l = task & 63;
            int hb = h * 32;
            u64 s2 = 0;
            #pragma unroll
            for (int kk = 0; kk < 32; ++kk) {
                u64 q2 = dup2(sm[OQA + l * 128 + hb + kk]);
                u64 kv = *reinterpret_cast<const u64*>(&sm[OKT + (hb + kk) * 66 + 2 * lane]);
                fma2(s2, q2, kv);
            }
            float sa, sb; unpk2(s2, sa, sb);
            sa *= 0.17677669529663687f;   // 1/sqrt(32)
            sb *= 0.17677669529663687f;
            float mx = fmaxf(sa, sb);
            #pragma unroll
            for (int o = 16; o > 0; o >>= 1)
                mx = fmaxf(mx, __shfl_xor_sync(0xffffffffu, mx, o));
            float ea = __expf(sa - mx), eb = __expf(sb - mx);
            float s = ea + eb;
            #pragma unroll
            for (int o = 16; o > 0; o >>= 1)
                s += __shfl_xor_sync(0xffffffffu, s, o);
            float inv = 1.0f / s;
            float pa = ea * inv, pb = eb * inv;
            u64 c2 = 0;
            #pragma unroll 8
            for (int m2 = 0; m2 < 32; ++m2) {
                float ba = __shfl_sync(0xffffffffu, pa, m2);
                float bb = __shfl_sync(0xffffffffu, pb, m2);
                u64 p2 = pk2(ba, bb);
                u64 vv = *reinterpret_cast<const u64*>(&sm[OVT + (hb + lane) * 66 + 2 * m2]);
                fma2(c2, p2, vv);
            }
            float c0, c1; unpk2(c2, c0, c1);
            sm[OCT + (hb + lane) * 66 + l] = c0 + c1;
        }
    }
    __syncthreads();

    // ---------------- phase 3: attended = ctx @ W_out^T + b_out (R1 verbatim) ----------------
    {
        const int txp = tid & 15;
        const int typ = tid >> 4;
        const int l0  = typ * 4;
        for (int t = 0; t < 2; ++t) {
            #pragma unroll
            for (int r = 0; r < 8; ++r) {
                int idx = tid + 256 * r;
                int e = idx >> 5, k4 = idx & 31;
                float4 w4 = *reinterpret_cast<const float4*>(
                    W_out + (size_t)(64 * t + e) * 128 + k4 * 4);
                int wb = OWS + e * 129 + k4 * 4;
                sm[wb] = w4.x; sm[wb + 1] = w4.y; sm[wb + 2] = w4.z; sm[wb + 3] = w4.w;
            }
            __syncthreads();

            u64 acc[8];
            #pragma unroll
            for (int j = 0; j < 4; ++j) {
                u64 bb = dup2(b_out[64 * t + txp + 16 * j]);
                acc[j] = bb; acc[4 + j] = bb;
            }
            #pragma unroll 4
            for (int kk = 0; kk < 128; ++kk) {
                u64 a0 = *reinterpret_cast<const u64*>(&sm[OCT + kk * 66 + l0]);
                u64 a1 = *reinterpret_cast<const u64*>(&sm[OCT + kk * 66 + l0 + 2]);
                #pragma unroll
                for (int j = 0; j < 4; ++j) {
                    u64 b2 = dup2(sm[OWS + (txp + 16 * j) * 129 + kk]);
                    fma2(acc[j],     a0, b2);
                    fma2(acc[4 + j], a1, b2);
                }
            }
            __syncthreads();
            #pragma unroll
            for (int j = 0; j < 4; ++j) {
                int eg = 64 * t + txp + 16 * j;
                float v0, v1;
                unpk2(acc[j], v0, v1);
                sm[OQA + l0 * 128 + eg]       = v0;
                sm[OQA + (l0 + 1) * 128 + eg] = v1;
                unpk2(acc[4 + j], v0, v1);
                sm[OQA + (l0 + 2) * 128 + eg] = v0;
                sm[OQA + (l0 + 3) * 128 + eg] = v1;
            }
        }
    }
    __syncthreads();

    // ---------------- phase 4: pooling + projections (R1 verbatim) ----------------
    #pragma unroll
    for (int i = 0; i < 8; ++i) {
        int l = warp * 8 + i;
        float p = 0.f;
        #pragma unroll
        for (int c = 0; c < 4; ++c) {
            int d = lane + 32 * c;
            p = fmaf(sm[OQA + l * 128 + d], sm[OXT + d * 66 + l], p);
        }
        #pragma unroll
        for (int o = 16; o > 0; o >>= 1) p += __shfl_xor_sync(0xffffffffu, p, o);
        if (lane == 0) sm[OAW + l] = p;
    }
    __syncthreads();
    if (warp == 0) {
        float va = sm[OAW + lane], vb = sm[OAW + lane + 32];
        float mx = fmaxf(va, vb);
        #pragma unroll
        for (int o = 16; o > 0; o >>= 1)
            mx = fmaxf(mx, __shfl_xor_sync(0xffffffffu, mx, o));
        float ea = __expf(va - mx), eb = __expf(vb - mx);
        float s = ea + eb;
        #pragma unroll
        for (int o = 16; o > 0; o >>= 1) s += __shfl_xor_sync(0xffffffffu, s, o);
        float inv = 1.0f / s;
        sm[OAW + lane]      = ea * inv;
        sm[OAW + lane + 32] = eb * inv;
    }
    __syncthreads();
    if (tid < 128) {
        int d = tid;
        float wacc = 0.f, s = 0.f, s2 = 0.f, mx = -3.4e38f;
        #pragma unroll 8
        for (int l = 0; l < 64; ++l) {
            float a = sm[OQA + l * 128 + d];
            wacc = fmaf(sm[OAW + l], a, wacc);
            s += a;
            s2 = fmaf(a, a, s2);
            mx = fmaxf(mx, a);
        }
        float mean = s * (1.0f / 64.0f);
        float var  = (s2 - s * mean) * (1.0f / 63.0f);
        sm[OPOOL + d]       = wacc;
        sm[OPOOL + 128 + d] = mx;
        sm[OPOOL + 256 + d] = mean;
        sm[OPOOL + 384 + d] = sqrtf(fmaxf(var, 0.0f));
    }
    __syncthreads();
    {
        int p  = warp >> 1;
        int f0 = (warp & 1) * 8;
        #pragma unroll
        for (int fi = 0; fi < 8; ++fi) {
            int o = p * 16 + f0 + fi;
            float acc = 0.f;
            #pragma unroll
            for (int c = 0; c < 4; ++c) {
                int d = lane + 32 * c;
                acc = fmaf(sm[OPOOL + p * 128 + d], W_pool[(size_t)o * 128 + d], acc);
            }
            #pragma unroll
            for (int off = 16; off > 0; off >>= 1)
                acc += __shfl_xor_sync(0xffffffffu, acc, off);
            if (lane == 0) out[(size_t)bm * 64 + o] = acc + b_pool[o];
        }
    }
}

extern "C" void kernel_launch(void* const* d_in, const int* in_sizes, int n_in,
                              void* d_out, int out_size)
{
    const float* x      = (const float*)d_in[0];
    const float* W_in   = (const float*)d_in[2];
    const float* b_in   = (const float*)d_in[3];
    const float* W_out  = (const float*)d_in[4];
    const float* b_out  = (const float*)d_in[5];
    const float* W_pool = (const float*)d_in[6];
    const float* b_pool = (const float*)d_in[7];
    float* out = (float*)d_out;

    int nmol = in_sizes[0] / (64 * 128);   // 8192

    prep_kernel<<<192, 256>>>(W_in);
    cudaFuncSetAttribute(feat_kernel,
                         cudaFuncAttributeMaxDynamicSharedMemorySize, SMEM_BYTES);
    feat_kernel<<<nmol, 256, SMEM_BYTES>>>(x, b_in, W_out, b_out,
                                           W_pool, b_pool, out);
}

// round 8
// speedup vs baseline: 1.5861x; 1.4608x over previous
#include <cuda_runtime.h>
#include <cuda_bf16.h>
#include <cstdint>

typedef unsigned long long u64;
typedef unsigned int u32;

// ---------- helpers ----------
__device__ __forceinline__ u64 pk2(float lo, float hi) {
    u64 r; asm("mov.b64 %0, {%1,%2};" : "=l"(r) : "f"(lo), "f"(hi)); return r;
}
__device__ __forceinline__ u64 dup2(float v) { return pk2(v, v); }
__device__ __forceinline__ void unpk2(u64 v, float &lo, float &hi) {
    asm("mov.b64 {%0,%1}, %2;" : "=f"(lo), "=f"(hi) : "l"(v));
}
__device__ __forceinline__ void fma2(u64 &d, u64 a, u64 b) {
    asm("fma.rn.f32x2 %0, %1, %2, %0;" : "+l"(d) : "l"(a), "l"(b));
}
// pack bf16(lo),bf16(hi) -> u32 (lo in low 16 bits)
__device__ __forceinline__ u32 bf2(float lo, float hi){
    u32 r; asm("cvt.rn.bf16x2.f32 %0, %1, %2;" : "=r"(r) : "f"(hi), "f"(lo)); return r;
}
__device__ __forceinline__ void mma16816(float* d, const u32* a, const u32* b){
    asm volatile("mma.sync.aligned.m16n8k16.row.col.f32.bf16.bf16.f32 "
        "{%0,%1,%2,%3}, {%4,%5,%6,%7}, {%8,%9}, {%0,%1,%2,%3};"
        : "+f"(d[0]),"+f"(d[1]),"+f"(d[2]),"+f"(d[3])
        : "r"(a[0]),"r"(a[1]),"r"(a[2]),"r"(a[3]), "r"(b[0]),"r"(b[1]));
}

// ---------- prepped weights: [512 rows][136] bf16 hi/lo (rows 0-383 W_in, 384-511 W_out) ----------
__device__ __align__(16) __nv_bfloat16 g_wh[512 * 136];
__device__ __align__(16) __nv_bfloat16 g_wl[512 * 136];

__global__ void prep_kernel(const float* __restrict__ W_in, const float* __restrict__ W_out){
    int idx = blockIdx.x * 256 + threadIdx.x;      // 65536
    int r = idx >> 7, c = idx & 127;
    float v = (r < 384) ? W_in[r * 128 + c] : W_out[(r - 384) * 128 + c];
    __nv_bfloat16 h = __float2bfloat16(v);
    float hf = __bfloat162float(h);
    g_wh[r * 136 + c] = h;
    g_wl[r * 136 + c] = __float2bfloat16(v - hf);
}

// ---------- smem layout (floats) ----------
#define OXT   0
#define OWS   8448
#define OCT   (OWS + 8256)
#define OKT   (OWS + 16704)
#define OVT   (OKT + 8448)
#define OQA   (OVT + 8448)
#define OPOOL (OQA + 8192)
#define OAW   (OPOOL + 512)
#define OPB   (OAW + 64)          // probs buffer: 8 warps x 256 floats
#define SMEM_FLOATS (OPB + 2048)
#define SMEM_BYTES  (SMEM_FLOATS * 4)   // 211,456 B
#define WLO 4352
#define SCL 0.17677669529663687f        // 1/sqrt(32)

__global__ void __launch_bounds__(256, 1)
feat_kernel(const float* __restrict__ xg_all,
            const float* __restrict__ b_in, const float* __restrict__ b_out,
            const float* __restrict__ W_pool, const float* __restrict__ b_pool,
            float* __restrict__ out)
{
    extern __shared__ float sm[];
    u32* smw = (u32*)sm;
    const int tid  = threadIdx.x;
    const int lane = tid & 31;
    const int warp = tid >> 5;
    const int bm   = blockIdx.x;
    const float* xg = xg_all + (size_t)bm * (64 * 128);

    // ---------------- phase 0: load x, transposed xT[d][l] ----------------
    #pragma unroll
    for (int r = 0; r < 8; ++r) {
        int idx = tid + 256 * r;              // 2048 float4 total
        int l = idx >> 5, k4 = idx & 31;
        float4 v = *reinterpret_cast<const float4*>(xg + l * 128 + k4 * 4);
        int base = OXT + (k4 * 4) * 66 + l;
        sm[base]       = v.x;
        sm[base + 66]  = v.y;
        sm[base + 132] = v.z;
        sm[base + 198] = v.w;
    }
    __syncthreads();

    // ---------------- phase 1: QKV via mma bf16 hi/lo (R6 verbatim) ----------------
    u32 Ah[32], Al[32];
    {
        const int s16 = (warp & 3) * 16;
        #pragma unroll
        for (int ks = 0; ks < 8; ++ks){
            #pragma unroll
            for (int q = 0; q < 4; ++q){
                int rr = s16 + (lane >> 2) + (q & 1) * 8;
                int k  = ks * 16 + 2 * (lane & 3) + (q >> 1) * 8;
                float f0 = sm[OXT + k * 66 + rr];
                float f1 = sm[OXT + (k + 1) * 66 + rr];
                u32 h = bf2(f0, f1);
                Ah[4 * ks + q] = h;
                float xr = __uint_as_float(h << 16);
                float yr = __uint_as_float(h & 0xffff0000u);
                Al[4 * ks + q] = bf2(f0 - xr, f1 - yr);
            }
        }
    }
    for (int si = 0; si < 6; ++si){
        __syncthreads();
        const uint4* srch = (const uint4*)(g_wh + (size_t)si * 8704);
        const uint4* srcl = (const uint4*)(g_wl + (size_t)si * 8704);
        uint4* dsth = (uint4*)&smw[OWS];
        uint4* dstl = (uint4*)&smw[OWS + WLO];
        for (int i = tid; i < 1088; i += 256){ dsth[i] = srch[i]; dstl[i] = srcl[i]; }
        __syncthreads();

        const int nh = warp >> 2;
        for (int j = 0; j < 4; ++j){
            float acc[4] = {0.f, 0.f, 0.f, 0.f};
            int bw = OWS + (nh * 32 + 8 * j + (lane >> 2)) * 68 + (lane & 3);
            #pragma unroll
            for (int p = 0; p < 4; ++p){
                u32 Bh[4], Bl[4];
                int bp = bw + p * 16;
                Bh[0] = smw[bp];      Bh[1] = smw[bp + 4];
                Bh[2] = smw[bp + 8];  Bh[3] = smw[bp + 12];
                Bl[0] = smw[bp + WLO];      Bl[1] = smw[bp + 4 + WLO];
                Bl[2] = smw[bp + 8 + WLO];  Bl[3] = smw[bp + 12 + WLO];
                mma16816(acc, &Ah[8*p],     &Bh[0]);
                mma16816(acc, &Ah[8*p],     &Bl[0]);
                mma16816(acc, &Al[8*p],     &Bh[0]);
                mma16816(acc, &Ah[8*p + 4], &Bh[2]);
                mma16816(acc, &Ah[8*p + 4], &Bl[2]);
                mma16816(acc, &Al[8*p + 4], &Bh[2]);
            }
            int e0 = si * 64 + nh * 32 + 8 * j + 2 * (lane & 3);
            int r0 = (warp & 3) * 16 + (lane >> 2);
            float v0 = acc[0] + b_in[e0];
            float v1 = acc[1] + b_in[e0 + 1];
            float v2 = acc[2] + b_in[e0];
            float v3 = acc[3] + b_in[e0 + 1];
            if (e0 < 128){
                sm[OQA + r0 * 128 + e0]           = v0;
                sm[OQA + r0 * 128 + e0 + 1]       = v1;
                sm[OQA + (r0 + 8) * 128 + e0]     = v2;
                sm[OQA + (r0 + 8) * 128 + e0 + 1] = v3;
            } else if (e0 < 256){
                int ek = e0 - 128;
                sm[OKT + ek * 66 + r0]           = v0;
                sm[OKT + (ek + 1) * 66 + r0]     = v1;
                sm[OKT + ek * 66 + r0 + 8]       = v2;
                sm[OKT + (ek + 1) * 66 + r0 + 8] = v3;
            } else {
                int ev = e0 - 256;
                sm[OVT + ev * 66 + r0]           = v0;
                sm[OVT + (ev + 1) * 66 + r0]     = v1;
                sm[OVT + ev * 66 + r0 + 8]       = v2;
                sm[OVT + (ev + 1) * 66 + r0 + 8] = v3;
            }
        }
    }
    __syncthreads();

    // ---------------- phase 2: attention, 4-row blocked ----------------
    {
        const int pbw = OPB + warp * 256;
        for (int it = 0; it < 8; ++it){
            int grp = warp * 8 + it;          // 0..63 = head*16 + rowblock
            int h = grp >> 4, l0 = (grp & 15) * 4, hb = h * 32;
            u64 s2[4] = {0, 0, 0, 0};
            #pragma unroll 8
            for (int kk = 0; kk < 32; ++kk){
                u64 kv = *(const u64*)&sm[OKT + (hb + kk) * 66 + 2 * lane];
                #pragma unroll
                for (int r = 0; r < 4; ++r)
                    fma2(s2[r], dup2(sm[OQA + (l0 + r) * 128 + hb + kk]), kv);
            }
            #pragma unroll
            for (int r = 0; r < 4; ++r){
                float sa, sb; unpk2(s2[r], sa, sb);
                sa *= SCL; sb *= SCL;
                float mx = fmaxf(sa, sb);
                #pragma unroll
                for (int o = 16; o > 0; o >>= 1)
                    mx = fmaxf(mx, __shfl_xor_sync(0xffffffffu, mx, o));
                float ea = __expf(sa - mx), eb = __expf(sb - mx);
                float s = ea + eb;
                #pragma unroll
                for (int o = 16; o > 0; o >>= 1)
                    s += __shfl_xor_sync(0xffffffffu, s, o);
                float inv = 1.0f / s;
                *(u64*)&sm[pbw + r * 64 + 2 * lane] = pk2(ea * inv, eb * inv);
            }
            __syncwarp();
            u64 c2[4] = {0, 0, 0, 0};
            #pragma unroll 4
            for (int m2 = 0; m2 < 32; ++m2){
                u64 vv = *(const u64*)&sm[OVT + (hb + lane) * 66 + 2 * m2];
                #pragma unroll
                for (int r = 0; r < 4; ++r)
                    fma2(c2[r], *(const u64*)&sm[pbw + r * 64 + 2 * m2], vv);
            }
            #pragma unroll
            for (int r = 0; r < 4; ++r){
                float c0, c1; unpk2(c2[r], c0, c1);
                sm[OCT + (hb + lane) * 66 + l0 + r] = c0 + c1;
            }
            __syncwarp();
        }
    }
    __syncthreads();

    // ---------------- phase 3: out-proj via mma bf16 hi/lo ----------------
    {
        const int s16 = (warp & 3) * 16;
        // A fragments from ctxT (stride 66), same pattern as QKV A build
        #pragma unroll
        for (int ks = 0; ks < 8; ++ks){
            #pragma unroll
            for (int q = 0; q < 4; ++q){
                int rr = s16 + (lane >> 2) + (q & 1) * 8;
                int k  = ks * 16 + 2 * (lane & 3) + (q >> 1) * 8;
                float f0 = sm[OCT + k * 66 + rr];
                float f1 = sm[OCT + (k + 1) * 66 + rr];
                u32 h = bf2(f0, f1);
                Ah[4 * ks + q] = h;
                float xr = __uint_as_float(h << 16);
                float yr = __uint_as_float(h & 0xffff0000u);
                Al[4 * ks + q] = bf2(f0 - xr, f1 - yr);
            }
        }
        for (int si = 0; si < 2; ++si){
            __syncthreads();
            // stage W_out rows [384 + si*64, +64) into OKT region (K^T/V^T dead now).
            // FULL 64 rows: 8704 bf16 hi = 1088 uint4; hi at OKT, lo at OKT+WLO..+8704 words
            // (spills 256 words into dead OVT — fine).
            const uint4* srch = (const uint4*)(g_wh + 52224 + (size_t)si * 8704);
            const uint4* srcl = (const uint4*)(g_wl + 52224 + (size_t)si * 8704);
            uint4* dsth = (uint4*)&smw[OKT];
            uint4* dstl = (uint4*)&smw[OKT + WLO];
            for (int i = tid; i < 1088; i += 256){ dsth[i] = srch[i]; dstl[i] = srcl[i]; }
            __syncthreads();

            const int nh = warp >> 2;
            for (int j = 0; j < 4; ++j){
                float acc[4] = {0.f, 0.f, 0.f, 0.f};
                int bw = OKT + (nh * 32 + 8 * j + (lane >> 2)) * 68 + (lane & 3);
                #pragma unroll
                for (int p = 0; p < 4; ++p){
                    u32 Bh[4], Bl[4];
                    int bp = bw + p * 16;
                    Bh[0] = smw[bp];      Bh[1] = smw[bp + 4];
                    Bh[2] = smw[bp + 8];  Bh[3] = smw[bp + 12];
                    Bl[0] = smw[bp + WLO];      Bl[1] = smw[bp + 4 + WLO];
                    Bl[2] = smw[bp + 8 + WLO];  Bl[3] = smw[bp + 12 + WLO];
                    mma16816(acc, &Ah[8*p],     &Bh[0]);
                    mma16816(acc, &Ah[8*p],     &Bl[0]);
                    mma16816(acc, &Al[8*p],     &Bh[0]);
                    mma16816(acc, &Ah[8*p + 4], &Bh[2]);
                    mma16816(acc, &Ah[8*p + 4], &Bl[2]);
                    mma16816(acc, &Al[8*p + 4], &Bh[2]);
                }
                int e0 = si * 64 + nh * 32 + 8 * j + 2 * (lane & 3);
                int r0 = s16 + (lane >> 2);
                sm[OQA + r0 * 128 + e0]           = acc[0] + b_out[e0];
                sm[OQA + r0 * 128 + e0 + 1]       = acc[1] + b_out[e0 + 1];
                sm[OQA + (r0 + 8) * 128 + e0]     = acc[2] + b_out[e0];
                sm[OQA + (r0 + 8) * 128 + e0 + 1] = acc[3] + b_out[e0 + 1];
            }
        }
    }
    __syncthreads();

    // ---------------- phase 4: pooling + projections (R1 verbatim) ----------------
    #pragma unroll
    for (int i = 0; i < 8; ++i) {
        int l = warp * 8 + i;
        float p = 0.f;
        #pragma unroll
        for (int c = 0; c < 4; ++c) {
            int d = lane + 32 * c;
            p = fmaf(sm[OQA + l * 128 + d], sm[OXT + d * 66 + l], p);
        }
        #pragma unroll
        for (int o = 16; o > 0; o >>= 1) p += __shfl_xor_sync(0xffffffffu, p, o);
        if (lane == 0) sm[OAW + l] = p;
    }
    __syncthreads();
    if (warp == 0) {
        float va = sm[OAW + lane], vb = sm[OAW + lane + 32];
        float mx = fmaxf(va, vb);
        #pragma unroll
        for (int o = 16; o > 0; o >>= 1)
            mx = fmaxf(mx, __shfl_xor_sync(0xffffffffu, mx, o));
        float ea = __expf(va - mx), eb = __expf(vb - mx);
        float s = ea + eb;
        #pragma unroll
        for (int o = 16; o > 0; o >>= 1) s += __shfl_xor_sync(0xffffffffu, s, o);
        float inv = 1.0f / s;
        sm[OAW + lane]      = ea * inv;
        sm[OAW + lane + 32] = eb * inv;
    }
    __syncthreads();
    if (tid < 128) {
        int d = tid;
        float wacc = 0.f, s = 0.f, s2 = 0.f, mx = -3.4e38f;
        #pragma unroll 8
        for (int l = 0; l < 64; ++l) {
            float a = sm[OQA + l * 128 + d];
            wacc = fmaf(sm[OAW + l], a, wacc);
            s += a;
            s2 = fmaf(a, a, s2);
            mx = fmaxf(mx, a);
        }
        float mean = s * (1.0f / 64.0f);
        float var  = (s2 - s * mean) * (1.0f / 63.0f);
        sm[OPOOL + d]       = wacc;
        sm[OPOOL + 128 + d] = mx;
        sm[OPOOL + 256 + d] = mean;
        sm[OPOOL + 384 + d] = sqrtf(fmaxf(var, 0.0f));
    }
    __syncthreads();
    {
        int p  = warp >> 1;
        int f0 = (warp & 1) * 8;
        #pragma unroll
        for (int fi = 0; fi < 8; ++fi) {
            int o = p * 16 + f0 + fi;
            float acc = 0.f;
            #pragma unroll
            for (int c = 0; c < 4; ++c) {
                int d = lane + 32 * c;
                acc = fmaf(sm[OPOOL + p * 128 + d], W_pool[(size_t)o * 128 + d], acc);
            }
            #pragma unroll
            for (int off = 16; off > 0; off >>= 1)
                acc += __shfl_xor_sync(0xffffffffu, acc, off);
            if (lane == 0) out[(size_t)bm * 64 + o] = acc + b_pool[o];
        }
    }
}

extern "C" void kernel_launch(void* const* d_in, const int* in_sizes, int n_in,
                              void* d_out, int out_size)
{
    const float* x      = (const float*)d_in[0];
    const float* W_in   = (const float*)d_in[2];
    const float* b_in   = (const float*)d_in[3];
    const float* W_out  = (const float*)d_in[4];
    const float* b_out  = (const float*)d_in[5];
    const float* W_pool = (const float*)d_in[6];
    const float* b_pool = (const float*)d_in[7];
    float* out = (float*)d_out;

    int nmol = in_sizes[0] / (64 * 128);   // 8192

    prep_kernel<<<256, 256>>>(W_in, W_out);
    cudaFuncSetAttribute(feat_kernel,
                         cudaFuncAttributeMaxDynamicSharedMemorySize, SMEM_BYTES);
    feat_kernel<<<nmol, 256, SMEM_BYTES>>>(x, b_in, b_out,
                                           W_pool, b_pool, out);
}

// round 9
// speedup vs baseline: 3.2845x; 2.0709x over previous
#include <cuda_runtime.h>
#include <cuda_bf16.h>
#include <cstdint>

typedef unsigned long long u64;
typedef unsigned int u32;

// ---------- helpers ----------
__device__ __forceinline__ u32 smem_u32(const void* p){
    u32 a; asm("{ .reg .u64 t; cvta.to.shared.u64 t, %1; cvt.u32.u64 %0, t; }" : "=r"(a) : "l"(p)); return a;
}
// pack bf16(lo),bf16(hi) -> u32 (lo in low 16 bits)
__device__ __forceinline__ u32 bf2(float lo, float hi){
    u32 r; asm("cvt.rn.bf16x2.f32 %0, %1, %2;" : "=r"(r) : "f"(hi), "f"(lo)); return r;
}
__device__ __forceinline__ void mma16816(float* d, const u32* a, const u32* b){
    asm volatile("mma.sync.aligned.m16n8k16.row.col.f32.bf16.bf16.f32 "
        "{%0,%1,%2,%3}, {%4,%5,%6,%7}, {%8,%9}, {%0,%1,%2,%3};"
        : "+f"(d[0]),"+f"(d[1]),"+f"(d[2]),"+f"(d[3])
        : "r"(a[0]),"r"(a[1]),"r"(a[2]),"r"(a[3]), "r"(b[0]),"r"(b[1]));
}
__device__ __forceinline__ void cpa16(u32 dst, const void* src){
    asm volatile("cp.async.cg.shared.global [%0], [%1], 16;" :: "r"(dst), "l"(src));
}
#define CPCOMMIT() asm volatile("cp.async.commit_group;" ::: "memory")
#define CPWAIT(n)  asm volatile("cp.async.wait_group %0;" :: "n"(n) : "memory")

// ---------- prepped weights: [512 rows][136] bf16 hi/lo (rows 0-383 W_in, 384-511 W_out) ----------
__device__ __align__(16) __nv_bfloat16 g_wh[512 * 136];
__device__ __align__(16) __nv_bfloat16 g_wl[512 * 136];

__global__ void prep_kernel(const float* __restrict__ W_in, const float* __restrict__ W_out){
    int idx = blockIdx.x * 256 + threadIdx.x;      // 65536
    int r = idx >> 7, c = idx & 127;
    float v = (r < 384) ? W_in[r * 128 + c] : W_out[(r - 384) * 128 + c];
    __nv_bfloat16 h = __float2bfloat16(v);
    float hf = __bfloat162float(h);
    g_wh[r * 136 + c] = h;
    g_wl[r * 136 + c] = __float2bfloat16(v - hf);
}

// ---------- smem layout (32-bit word indices) ----------
#define OWSA  0          // W stage buf A: hi 4352 + lo 4352
#define OWSB  8704
#define OKH   17408      // K bf16 hi [64 rows][68 words]
#define OKL   21760
#define OVTH  26112      // V^T bf16 hi [128 d][36 words]
#define OVTL  30720
#define OCXH  35328      // ctx bf16 hi [64 rows][68 words]
#define OCXL  39680
#define OQA   44032      // attended fp32 [64][128]
#define OPOOL 52224
#define OAW   52736
#define SMEM_FLOATS 52800
#define SMEM_BYTES  (SMEM_FLOATS * 4)   // 211,200 B
#define WLO 4352
#define SCL 0.17677669529663687f        // 1/sqrt(32)

__device__ __forceinline__ void issue_stage(int tid, int s, u32 bufw, u32 smb){
    const __nv_bfloat16* sh = g_wh + (size_t)s * 8704;
    const __nv_bfloat16* sl = g_wl + (size_t)s * 8704;
    for (int i = tid; i < 1088; i += 256){
        cpa16(smb + (bufw + (u32)i * 4) * 4,        sh + i * 8);
        cpa16(smb + (bufw + WLO + (u32)i * 4) * 4,  sl + i * 8);
    }
}

__global__ void __launch_bounds__(256, 1)
feat_kernel(const float* __restrict__ xg_all,
            const float* __restrict__ b_in, const float* __restrict__ b_out,
            const float* __restrict__ W_pool, const float* __restrict__ b_pool,
            float* __restrict__ out)
{
    extern __shared__ float sm[];
    u32* smw = (u32*)sm;
    const u32 smb = smem_u32(sm);
    const int tid  = threadIdx.x;
    const int lane = tid & 31;
    const int warp = tid >> 5;
    const int q4   = lane >> 2;        // 0..7
    const int t4   = lane & 3;         // 0..3
    const int s16  = (warp & 3) * 16;  // row stripe
    const int nh   = warp >> 2;        // 0/1 column half
    const int bm   = blockIdx.x;
    const float* xg = xg_all + (size_t)bm * (64 * 128);

    // prefetch W stages 0,1
    issue_stage(tid, 0, OWSA, smb); CPCOMMIT();
    issue_stage(tid, 1, OWSB, smb); CPCOMMIT();

    // ---- A fragments from gmem x (hi/lo) ----
    u32 Ah[32], Al[32];
    #pragma unroll
    for (int ks = 0; ks < 8; ++ks){
        #pragma unroll
        for (int qq = 0; qq < 4; ++qq){
            int rr = s16 + q4 + (qq & 1) * 8;
            int k  = ks * 16 + 2 * t4 + (qq >> 1) * 8;
            float2 v = *(const float2*)(xg + rr * 128 + k);
            u32 h = bf2(v.x, v.y);
            Ah[4 * ks + qq] = h;
            float xr = __uint_as_float(h << 16);
            float yr = __uint_as_float(h & 0xffff0000u);
            Al[4 * ks + qq] = bf2(v.x - xr, v.y - yr);
        }
    }

    u32 QAh[16], QAl[16];   // Q A-frags: 2 heads x 2 ksteps x 4

    // ---------------- QKV, double-buffered ----------------
    for (int si = 0; si < 6; ++si){
        CPWAIT(1);
        __syncthreads();
        const u32 bufw = (si & 1) ? OWSB : OWSA;
        for (int j = 0; j < 4; ++j){
            float acc[4] = {0.f, 0.f, 0.f, 0.f};
            int bw = bufw + (u32)(nh * 32 + 8 * j + q4) * 68 + t4;
            #pragma unroll
            for (int p = 0; p < 4; ++p){
                u32 Bh[4], Bl[4];
                int bp = bw + p * 16;
                Bh[0] = smw[bp];      Bh[1] = smw[bp + 4];
                Bh[2] = smw[bp + 8];  Bh[3] = smw[bp + 12];
                Bl[0] = smw[bp + WLO];      Bl[1] = smw[bp + 4 + WLO];
                Bl[2] = smw[bp + 8 + WLO];  Bl[3] = smw[bp + 12 + WLO];
                mma16816(acc, &Ah[8*p],     &Bh[0]);
                mma16816(acc, &Ah[8*p],     &Bl[0]);
                mma16816(acc, &Al[8*p],     &Bh[0]);
                mma16816(acc, &Ah[8*p + 4], &Bh[2]);
                mma16816(acc, &Ah[8*p + 4], &Bl[2]);
                mma16816(acc, &Al[8*p + 4], &Bh[2]);
            }
            int e0 = si * 64 + nh * 32 + 8 * j + 2 * t4;
            int r0 = s16 + q4;
            float v0 = acc[0] + b_in[e0];
            float v1 = acc[1] + b_in[e0 + 1];
            float v2 = acc[2] + b_in[e0];
            float v3 = acc[3] + b_in[e0 + 1];
            if (si < 2){
                // Q -> register A-frags (scaled)
                v0 *= SCL; v1 *= SCL; v2 *= SCL; v3 *= SCL;
                int base = si * 8 + (j >> 1) * 4 + (j & 1) * 2;
                u32 h0 = bf2(v0, v1), h1 = bf2(v2, v3);
                QAh[base]     = h0;
                QAh[base + 1] = h1;
                float a0 = __uint_as_float(h0 << 16), a1 = __uint_as_float(h0 & 0xffff0000u);
                float c0 = __uint_as_float(h1 << 16), c1 = __uint_as_float(h1 & 0xffff0000u);
                QAl[base]     = bf2(v0 - a0, v1 - a1);
                QAl[base + 1] = bf2(v2 - c0, v3 - c1);
            } else if (si < 4){
                // K row-major bf16 hi/lo
                int kw = (si - 2) * 32 + nh * 16 + 4 * j + t4;
                u32 h0 = bf2(v0, v1), h1 = bf2(v2, v3);
                smw[OKH + r0 * 68 + kw]       = h0;
                smw[OKH + (r0 + 8) * 68 + kw] = h1;
                float a0 = __uint_as_float(h0 << 16), a1 = __uint_as_float(h0 & 0xffff0000u);
                float c0 = __uint_as_float(h1 << 16), c1 = __uint_as_float(h1 & 0xffff0000u);
                smw[OKL + r0 * 68 + kw]       = bf2(v0 - a0, v1 - a1);
                smw[OKL + (r0 + 8) * 68 + kw] = bf2(v2 - c0, v3 - c1);
            } else {
                // V^T bf16 hi/lo (halfword stores)
                int d0 = (si - 4) * 64 + nh * 32 + 8 * j + 2 * t4;
                __nv_bfloat16* vth = (__nv_bfloat16*)&smw[OVTH];
                __nv_bfloat16* vtl = (__nv_bfloat16*)&smw[OVTL];
                __nv_bfloat16 h0 = __float2bfloat16(v0);
                __nv_bfloat16 h1 = __float2bfloat16(v1);
                __nv_bfloat16 h2 = __float2bfloat16(v2);
                __nv_bfloat16 h3 = __float2bfloat16(v3);
                vth[d0 * 72 + r0]           = h0;
                vth[(d0 + 1) * 72 + r0]     = h1;
                vth[d0 * 72 + r0 + 8]       = h2;
                vth[(d0 + 1) * 72 + r0 + 8] = h3;
                vtl[d0 * 72 + r0]           = __float2bfloat16(v0 - __bfloat162float(h0));
                vtl[(d0 + 1) * 72 + r0]     = __float2bfloat16(v1 - __bfloat162float(h1));
                vtl[d0 * 72 + r0 + 8]       = __float2bfloat16(v2 - __bfloat162float(h2));
                vtl[(d0 + 1) * 72 + r0 + 8] = __float2bfloat16(v3 - __bfloat162float(h3));
            }
        }
        __syncthreads();
        issue_stage(tid, si + 2, bufw, smb); CPCOMMIT();   // si+2 in [2,7]; 6,7 = W_out
    }
    __syncthreads();   // K/V visible to all

    // ---------------- attention: mma, 2 heads per warp ----------------
    {
        const int r0 = s16 + q4;
        float Sf[32];          // 8 nb x 4
        u32 Pa[16], Pl[16];    // P frags: 4 ksteps x 4
        float C2[16];          // 4 nb2 x 4
        #pragma unroll
        for (int hid = 0; hid < 2; ++hid){
            int h = nh + 2 * hid;
            #pragma unroll
            for (int i = 0; i < 32; ++i) Sf[i] = 0.f;
            // S = Q.K^T
            #pragma unroll
            for (int nb = 0; nb < 8; ++nb){
                int base = OKH + (8 * nb + q4) * 68 + h * 16 + t4;
                #pragma unroll
                for (int ks = 0; ks < 2; ++ks){
                    u32 Bh[2] = { smw[base + 8*ks], smw[base + 8*ks + 4] };
                    u32 Bl[2] = { smw[base + 8*ks + (OKL - OKH)], smw[base + 8*ks + 4 + (OKL - OKH)] };
                    mma16816(&Sf[nb*4], &QAh[hid*8 + ks*4], Bh);
                    mma16816(&Sf[nb*4], &QAh[hid*8 + ks*4], Bl);
                    mma16816(&Sf[nb*4], &QAl[hid*8 + ks*4], Bh);
                }
            }
            // fragment softmax: rows r0 (idx 0,1) and r0+8 (idx 2,3)
            float mx0 = -3.4e38f, mx1 = -3.4e38f;
            #pragma unroll
            for (int nb = 0; nb < 8; ++nb){
                mx0 = fmaxf(mx0, fmaxf(Sf[nb*4],     Sf[nb*4 + 1]));
                mx1 = fmaxf(mx1, fmaxf(Sf[nb*4 + 2], Sf[nb*4 + 3]));
            }
            mx0 = fmaxf(mx0, __shfl_xor_sync(0xffffffffu, mx0, 1));
            mx0 = fmaxf(mx0, __shfl_xor_sync(0xffffffffu, mx0, 2));
            mx1 = fmaxf(mx1, __shfl_xor_sync(0xffffffffu, mx1, 1));
            mx1 = fmaxf(mx1, __shfl_xor_sync(0xffffffffu, mx1, 2));
            float sum0 = 0.f, sum1 = 0.f;
            #pragma unroll
            for (int nb = 0; nb < 8; ++nb){
                Sf[nb*4]     = __expf(Sf[nb*4]     - mx0);
                Sf[nb*4 + 1] = __expf(Sf[nb*4 + 1] - mx0);
                Sf[nb*4 + 2] = __expf(Sf[nb*4 + 2] - mx1);
                Sf[nb*4 + 3] = __expf(Sf[nb*4 + 3] - mx1);
                sum0 += Sf[nb*4] + Sf[nb*4 + 1];
                sum1 += Sf[nb*4 + 2] + Sf[nb*4 + 3];
            }
            sum0 += __shfl_xor_sync(0xffffffffu, sum0, 1);
            sum0 += __shfl_xor_sync(0xffffffffu, sum0, 2);
            sum1 += __shfl_xor_sync(0xffffffffu, sum1, 1);
            sum1 += __shfl_xor_sync(0xffffffffu, sum1, 2);
            float inv0 = 1.0f / sum0, inv1 = 1.0f / sum1;
            // P frags (hi/lo)
            #pragma unroll
            for (int k2 = 0; k2 < 4; ++k2){
                float p00 = Sf[(2*k2)*4]     * inv0, p01 = Sf[(2*k2)*4 + 1] * inv0;
                float p10 = Sf[(2*k2)*4 + 2] * inv1, p11 = Sf[(2*k2)*4 + 3] * inv1;
                float p20 = Sf[(2*k2+1)*4]     * inv0, p21 = Sf[(2*k2+1)*4 + 1] * inv0;
                float p30 = Sf[(2*k2+1)*4 + 2] * inv1, p31 = Sf[(2*k2+1)*4 + 3] * inv1;
                u32 h0 = bf2(p00, p01), h1 = bf2(p10, p11);
                u32 h2 = bf2(p20, p21), h3 = bf2(p30, p31);
                Pa[k2*4]     = h0; Pa[k2*4 + 1] = h1;
                Pa[k2*4 + 2] = h2; Pa[k2*4 + 3] = h3;
                Pl[k2*4]     = bf2(p00 - __uint_as_float(h0 << 16), p01 - __uint_as_float(h0 & 0xffff0000u));
                Pl[k2*4 + 1] = bf2(p10 - __uint_as_float(h1 << 16), p11 - __uint_as_float(h1 & 0xffff0000u));
                Pl[k2*4 + 2] = bf2(p20 - __uint_as_float(h2 << 16), p21 - __uint_as_float(h2 & 0xffff0000u));
                Pl[k2*4 + 3] = bf2(p30 - __uint_as_float(h3 << 16), p31 - __uint_as_float(h3 & 0xffff0000u));
            }
            // ctx = P.V
            #pragma unroll
            for (int i = 0; i < 16; ++i) C2[i] = 0.f;
            #pragma unroll
            for (int nb2 = 0; nb2 < 4; ++nb2){
                int vbase = OVTH + (h * 32 + 8 * nb2 + q4) * 36 + t4;
                #pragma unroll
                for (int k2 = 0; k2 < 4; ++k2){
                    u32 Bh[2] = { smw[vbase + 8*k2], smw[vbase + 8*k2 + 4] };
                    u32 Bl[2] = { smw[vbase + 8*k2 + (OVTL - OVTH)], smw[vbase + 8*k2 + 4 + (OVTL - OVTH)] };
                    mma16816(&C2[nb2*4], &Pa[k2*4], Bh);
                    mma16816(&C2[nb2*4], &Pa[k2*4], Bl);
                    mma16816(&C2[nb2*4], &Pl[k2*4], Bh);
                }
            }
            // ctx writeback as bf16 hi/lo A-layout
            #pragma unroll
            for (int nb2 = 0; nb2 < 4; ++nb2){
                int w = h * 16 + 4 * nb2 + t4;
                u32 h0 = bf2(C2[nb2*4],     C2[nb2*4 + 1]);
                u32 h1 = bf2(C2[nb2*4 + 2], C2[nb2*4 + 3]);
                smw[OCXH + r0 * 68 + w]       = h0;
                smw[OCXH + (r0 + 8) * 68 + w] = h1;
                smw[OCXL + r0 * 68 + w] =
                    bf2(C2[nb2*4]     - __uint_as_float(h0 << 16),
                        C2[nb2*4 + 1] - __uint_as_float(h0 & 0xffff0000u));
                smw[OCXL + (r0 + 8) * 68 + w] =
                    bf2(C2[nb2*4 + 2] - __uint_as_float(h1 << 16),
                        C2[nb2*4 + 3] - __uint_as_float(h1 & 0xffff0000u));
            }
        }
    }
    CPWAIT(0);
    __syncthreads();

    // ---------------- out-proj: ctx(bf16) @ W_out^T + b_out -> QA ----------------
    {
        #pragma unroll
        for (int ks = 0; ks < 8; ++ks){
            int a0 = OCXH + (s16 + q4) * 68 + 8 * ks + t4;
            Ah[ks*4]     = smw[a0];
            Ah[ks*4 + 1] = smw[a0 + 8 * 68];
            Ah[ks*4 + 2] = smw[a0 + 4];
            Ah[ks*4 + 3] = smw[a0 + 8 * 68 + 4];
            Al[ks*4]     = smw[a0 + (OCXL - OCXH)];
            Al[ks*4 + 1] = smw[a0 + 8 * 68 + (OCXL - OCXH)];
            Al[ks*4 + 2] = smw[a0 + 4 + (OCXL - OCXH)];
            Al[ks*4 + 3] = smw[a0 + 8 * 68 + 4 + (OCXL - OCXH)];
        }
        for (int si = 0; si < 2; ++si){
            const u32 bufw = si ? OWSB : OWSA;
            for (int j = 0; j < 4; ++j){
                float acc[4] = {0.f, 0.f, 0.f, 0.f};
                int bw = bufw + (u32)(nh * 32 + 8 * j + q4) * 68 + t4;
                #pragma unroll
                for (int p = 0; p < 4; ++p){
                    u32 Bh[4], Bl[4];
                    int bp = bw + p * 16;
                    Bh[0] = smw[bp];      Bh[1] = smw[bp + 4];
                    Bh[2] = smw[bp + 8];  Bh[3] = smw[bp + 12];
                    Bl[0] = smw[bp + WLO];      Bl[1] = smw[bp + 4 + WLO];
                    Bl[2] = smw[bp + 8 + WLO];  Bl[3] = smw[bp + 12 + WLO];
                    mma16816(acc, &Ah[8*p],     &Bh[0]);
                    mma16816(acc, &Ah[8*p],     &Bl[0]);
                    mma16816(acc, &Al[8*p],     &Bh[0]);
                    mma16816(acc, &Ah[8*p + 4], &Bh[2]);
                    mma16816(acc, &Ah[8*p + 4], &Bl[2]);
                    mma16816(acc, &Al[8*p + 4], &Bh[2]);
                }
                int e0 = si * 64 + nh * 32 + 8 * j + 2 * t4;
                int r0 = s16 + q4;
                sm[OQA + r0 * 128 + e0]           = acc[0] + b_out[e0];
                sm[OQA + r0 * 128 + e0 + 1]       = acc[1] + b_out[e0 + 1];
                sm[OQA + (r0 + 8) * 128 + e0]     = acc[2] + b_out[e0];
                sm[OQA + (r0 + 8) * 128 + e0 + 1] = acc[3] + b_out[e0 + 1];
            }
        }
    }
    __syncthreads();

    // ---------------- pooling + projections ----------------
    #pragma unroll
    for (int i = 0; i < 8; ++i) {
        int l = warp * 8 + i;
        float p = 0.f;
        #pragma unroll
        for (int c = 0; c < 4; ++c) {
            int d = lane + 32 * c;
            p = fmaf(sm[OQA + l * 128 + d], xg[l * 128 + d], p);
        }
        #pragma unroll
        for (int o = 16; o > 0; o >>= 1) p += __shfl_xor_sync(0xffffffffu, p, o);
        if (lane == 0) sm[OAW + l] = p;
    }
    __syncthreads();
    if (warp == 0) {
        float va = sm[OAW + lane], vb = sm[OAW + lane + 32];
        float mx = fmaxf(va, vb);
        #pragma unroll
        for (int o = 16; o > 0; o >>= 1)
            mx = fmaxf(mx, __shfl_xor_sync(0xffffffffu, mx, o));
        float ea = __expf(va - mx), eb = __expf(vb - mx);
        float s = ea + eb;
        #pragma unroll
        for (int o = 16; o > 0; o >>= 1) s += __shfl_xor_sync(0xffffffffu, s, o);
        float inv = 1.0f / s;
        sm[OAW + lane]      = ea * inv;
        sm[OAW + lane + 32] = eb * inv;
    }
    __syncthreads();
    if (tid < 128) {
        int d = tid;
        float wacc = 0.f, s = 0.f, s2 = 0.f, mx = -3.4e38f;
        #pragma unroll 8
        for (int l = 0; l < 64; ++l) {
            float a = sm[OQA + l * 128 + d];
            wacc = fmaf(sm[OAW + l], a, wacc);
            s += a;
            s2 = fmaf(a, a, s2);
            mx = fmaxf(mx, a);
        }
        float mean = s * (1.0f / 64.0f);
        float var  = (s2 - s * mean) * (1.0f / 63.0f);
        sm[OPOOL + d]       = wacc;
        sm[OPOOL + 128 + d] = mx;
        sm[OPOOL + 256 + d] = mean;
        sm[OPOOL + 384 + d] = sqrtf(fmaxf(var, 0.0f));
    }
    __syncthreads();
    {
        int p  = warp >> 1;
        int f0 = (warp & 1) * 8;
        #pragma unroll
        for (int fi = 0; fi < 8; ++fi) {
            int o = p * 16 + f0 + fi;
            float acc = 0.f;
            #pragma unroll
            for (int c = 0; c < 4; ++c) {
                int d = lane + 32 * c;
                acc = fmaf(sm[OPOOL + p * 128 + d], W_pool[(size_t)o * 128 + d], acc);
            }
            #pragma unroll
            for (int off = 16; off > 0; off >>= 1)
                acc += __shfl_xor_sync(0xffffffffu, acc, off);
            if (lane == 0) out[(size_t)bm * 64 + o] = acc + b_pool[o];
        }
    }
}

extern "C" void kernel_launch(void* const* d_in, const int* in_sizes, int n_in,
                              void* d_out, int out_size)
{
    const float* x      = (const float*)d_in[0];
    const float* W_in   = (const float*)d_in[2];
    const float* b_in   = (const float*)d_in[3];
    const float* W_out  = (const float*)d_in[4];
    const float* b_out  = (const float*)d_in[5];
    const float* W_pool = (const float*)d_in[6];
    const float* b_pool = (const float*)d_in[7];
    float* out = (float*)d_out;

    int nmol = in_sizes[0] / (64 * 128);   // 8192

    prep_kernel<<<256, 256>>>(W_in, W_out);
    cudaFuncSetAttribute(feat_kernel,
                         cudaFuncAttributeMaxDynamicSharedMemorySize, SMEM_BYTES);
    feat_kernel<<<nmol, 256, SMEM_BYTES>>>(x, b_in, b_out,
                                           W_pool, b_pool, out);
}

// round 10
// speedup vs baseline: 3.5706x; 1.0871x over previous
#include <cuda_runtime.h>
#include <cuda_bf16.h>
#include <cstdint>

typedef unsigned long long u64;
typedef unsigned int u32;

// ---------- helpers ----------
__device__ __forceinline__ u32 smem_u32(const void* p){
    u32 a; asm("{ .reg .u64 t; cvta.to.shared.u64 t, %1; cvt.u32.u64 %0, t; }" : "=r"(a) : "l"(p)); return a;
}
// pack bf16(lo),bf16(hi) -> u32 (lo in low 16 bits)
__device__ __forceinline__ u32 bf2(float lo, float hi){
    u32 r; asm("cvt.rn.bf16x2.f32 %0, %1, %2;" : "=r"(r) : "f"(hi), "f"(lo)); return r;
}
__device__ __forceinline__ void mma16816(float* d, const u32* a, const u32* b){
    asm volatile("mma.sync.aligned.m16n8k16.row.col.f32.bf16.bf16.f32 "
        "{%0,%1,%2,%3}, {%4,%5,%6,%7}, {%8,%9}, {%0,%1,%2,%3};"
        : "+f"(d[0]),"+f"(d[1]),"+f"(d[2]),"+f"(d[3])
        : "r"(a[0]),"r"(a[1]),"r"(a[2]),"r"(a[3]), "r"(b[0]),"r"(b[1]));
}
__device__ __forceinline__ void cpa16(u32 dst, const void* src){
    asm volatile("cp.async.cg.shared.global [%0], [%1], 16;" :: "r"(dst), "l"(src));
}
#define CPCOMMIT() asm volatile("cp.async.commit_group;" ::: "memory")
#define CPWAIT(n)  asm volatile("cp.async.wait_group %0;" :: "n"(n) : "memory")

// ---------- prepped weights: [512 rows][136] bf16 hi/lo (rows 0-383 W_in, 384-511 W_out) ----------
__device__ __align__(16) __nv_bfloat16 g_wh[512 * 136];
__device__ __align__(16) __nv_bfloat16 g_wl[512 * 136];

__global__ void prep_kernel(const float* __restrict__ W_in, const float* __restrict__ W_out){
    int idx = blockIdx.x * 256 + threadIdx.x;      // 65536
    int r = idx >> 7, c = idx & 127;
    float v = (r < 384) ? W_in[r * 128 + c] : W_out[(r - 384) * 128 + c];
    __nv_bfloat16 h = __float2bfloat16(v);
    float hf = __bfloat162float(h);
    g_wh[r * 136 + c] = h;
    g_wl[r * 136 + c] = __float2bfloat16(v - hf);
}

// ---------- smem layout (32-bit word indices) ----------
#define OWSA  0          // W stage buf A: hi 4352 + lo 4352
#define OWSB  8704
#define OKH   17408      // K bf16 hi [64 rows][68 words]
#define OKL   21760
#define OVTH  26112      // V^T bf16 hi [128 d][36 words]
#define OVTL  30720
#define OCXH  35328      // ctx bf16 hi [64 rows][68 words]
#define OCXL  39680
#define OQH   44032      // Q bf16 hi [64 rows][68 words] (dead after attention)
#define OQL   48384
#define OQA   44032      // attended fp32 [64][128] — overlaps Q (temporally disjoint)
#define OPOOL 52736
#define OAW   53248
#define SMEM_FLOATS 53312
#define SMEM_BYTES  (SMEM_FLOATS * 4)   // 213,248 B
#define WLO 4352
#define SCL 0.17677669529663687f        // 1/sqrt(32)

#define NT 512

__device__ __forceinline__ void issue_stage(int tid, int s, u32 bufw, u32 smb){
    const __nv_bfloat16* sh = g_wh + (size_t)s * 8704;
    const __nv_bfloat16* sl = g_wl + (size_t)s * 8704;
    for (int i = tid; i < 1088; i += NT){
        cpa16(smb + (bufw + (u32)i * 4) * 4,        sh + i * 8);
        cpa16(smb + (bufw + WLO + (u32)i * 4) * 4,  sl + i * 8);
    }
}

__global__ void __launch_bounds__(NT, 1)
feat_kernel(const float* __restrict__ xg_all,
            const float* __restrict__ b_in, const float* __restrict__ b_out,
            const float* __restrict__ W_pool, const float* __restrict__ b_pool,
            float* __restrict__ out)
{
    extern __shared__ float sm[];
    u32* smw = (u32*)sm;
    const u32 smb = smem_u32(sm);
    const int tid  = threadIdx.x;
    const int lane = tid & 31;
    const int warp = tid >> 5;        // 0..15
    const int q4   = lane >> 2;       // 0..7
    const int t4   = lane & 3;        // 0..3
    const int s16  = (warp & 3) * 16; // row stripe
    const int nq   = warp >> 2;       // 0..3 column quarter
    const int bm   = blockIdx.x;
    const float* xg = xg_all + (size_t)bm * (64 * 128);

    // prefetch W stages 0,1
    issue_stage(tid, 0, OWSA, smb); CPCOMMIT();
    issue_stage(tid, 1, OWSB, smb); CPCOMMIT();

    // ---- A fragments from gmem x (hi/lo) ----
    u32 Ah[32], Al[32];
    #pragma unroll
    for (int ks = 0; ks < 8; ++ks){
        #pragma unroll
        for (int qq = 0; qq < 4; ++qq){
            int rr = s16 + q4 + (qq & 1) * 8;
            int k  = ks * 16 + 2 * t4 + (qq >> 1) * 8;
            float2 v = *(const float2*)(xg + rr * 128 + k);
            u32 h = bf2(v.x, v.y);
            Ah[4 * ks + qq] = h;
            float xr = __uint_as_float(h << 16);
            float yr = __uint_as_float(h & 0xffff0000u);
            Al[4 * ks + qq] = bf2(v.x - xr, v.y - yr);
        }
    }

    // ---------------- QKV, double-buffered ----------------
    for (int si = 0; si < 6; ++si){
        CPWAIT(1);
        __syncthreads();
        const u32 bufw = (si & 1) ? OWSB : OWSA;
        for (int j = 0; j < 2; ++j){
            float acc[4] = {0.f, 0.f, 0.f, 0.f};
            int bw = bufw + (u32)(nq * 16 + 8 * j + q4) * 68 + t4;
            #pragma unroll
            for (int p = 0; p < 4; ++p){
                u32 Bh[4], Bl[4];
                int bp = bw + p * 16;
                Bh[0] = smw[bp];      Bh[1] = smw[bp + 4];
                Bh[2] = smw[bp + 8];  Bh[3] = smw[bp + 12];
                Bl[0] = smw[bp + WLO];      Bl[1] = smw[bp + 4 + WLO];
                Bl[2] = smw[bp + 8 + WLO];  Bl[3] = smw[bp + 12 + WLO];
                mma16816(acc, &Ah[8*p],     &Bh[0]);
                mma16816(acc, &Ah[8*p],     &Bl[0]);
                mma16816(acc, &Al[8*p],     &Bh[0]);
                mma16816(acc, &Ah[8*p + 4], &Bh[2]);
                mma16816(acc, &Ah[8*p + 4], &Bl[2]);
                mma16816(acc, &Al[8*p + 4], &Bh[2]);
            }
            int e0 = si * 64 + nq * 16 + 8 * j + 2 * t4;
            int r0 = s16 + q4;
            float v0 = acc[0] + b_in[e0];
            float v1 = acc[1] + b_in[e0 + 1];
            float v2 = acc[2] + b_in[e0];
            float v3 = acc[3] + b_in[e0 + 1];
            if (si < 2){
                // Q (scaled) -> smem bf16 hi/lo A-layout [row][68 words]
                v0 *= SCL; v1 *= SCL; v2 *= SCL; v3 *= SCL;
                int w = si * 32 + nq * 8 + 4 * j + t4;
                u32 h0 = bf2(v0, v1), h1 = bf2(v2, v3);
                smw[OQH + r0 * 68 + w]       = h0;
                smw[OQH + (r0 + 8) * 68 + w] = h1;
                smw[OQL + r0 * 68 + w] =
                    bf2(v0 - __uint_as_float(h0 << 16), v1 - __uint_as_float(h0 & 0xffff0000u));
                smw[OQL + (r0 + 8) * 68 + w] =
                    bf2(v2 - __uint_as_float(h1 << 16), v3 - __uint_as_float(h1 & 0xffff0000u));
            } else if (si < 4){
                // K row-major bf16 hi/lo
                int kw = (si - 2) * 32 + nq * 8 + 4 * j + t4;
                u32 h0 = bf2(v0, v1), h1 = bf2(v2, v3);
                smw[OKH + r0 * 68 + kw]       = h0;
                smw[OKH + (r0 + 8) * 68 + kw] = h1;
                smw[OKL + r0 * 68 + kw] =
                    bf2(v0 - __uint_as_float(h0 << 16), v1 - __uint_as_float(h0 & 0xffff0000u));
                smw[OKL + (r0 + 8) * 68 + kw] =
                    bf2(v2 - __uint_as_float(h1 << 16), v3 - __uint_as_float(h1 & 0xffff0000u));
            } else {
                // V^T bf16 hi/lo (halfword stores)
                int d0 = (si - 4) * 64 + nq * 16 + 8 * j + 2 * t4;
                __nv_bfloat16* vth = (__nv_bfloat16*)&smw[OVTH];
                __nv_bfloat16* vtl = (__nv_bfloat16*)&smw[OVTL];
                __nv_bfloat16 h0 = __float2bfloat16(v0);
                __nv_bfloat16 h1 = __float2bfloat16(v1);
                __nv_bfloat16 h2 = __float2bfloat16(v2);
                __nv_bfloat16 h3 = __float2bfloat16(v3);
                vth[d0 * 72 + r0]           = h0;
                vth[(d0 + 1) * 72 + r0]     = h1;
                vth[d0 * 72 + r0 + 8]       = h2;
                vth[(d0 + 1) * 72 + r0 + 8] = h3;
                vtl[d0 * 72 + r0]           = __float2bfloat16(v0 - __bfloat162float(h0));
                vtl[(d0 + 1) * 72 + r0]     = __float2bfloat16(v1 - __bfloat162float(h1));
                vtl[d0 * 72 + r0 + 8]       = __float2bfloat16(v2 - __bfloat162float(h2));
                vtl[(d0 + 1) * 72 + r0 + 8] = __float2bfloat16(v3 - __bfloat162float(h3));
            }
        }
        __syncthreads();
        issue_stage(tid, si + 2, bufw, smb); CPCOMMIT();   // si+2 in [2,7]; 6,7 = W_out
    }
    __syncthreads();   // Q/K/V visible to all

    // ---------------- attention: mma, ONE head per warp (h = nq) ----------------
    {
        const int r0 = s16 + q4;
        const int h = nq;
        // Q A-frags from smem (2 ksteps x 4)
        u32 QAh[8], QAl[8];
        #pragma unroll
        for (int ks = 0; ks < 2; ++ks){
            int a0 = OQH + r0 * 68 + h * 16 + 8 * ks + t4;
            QAh[ks*4]     = smw[a0];
            QAh[ks*4 + 1] = smw[a0 + 8 * 68];
            QAh[ks*4 + 2] = smw[a0 + 4];
            QAh[ks*4 + 3] = smw[a0 + 8 * 68 + 4];
            QAl[ks*4]     = smw[a0 + (OQL - OQH)];
            QAl[ks*4 + 1] = smw[a0 + 8 * 68 + (OQL - OQH)];
            QAl[ks*4 + 2] = smw[a0 + 4 + (OQL - OQH)];
            QAl[ks*4 + 3] = smw[a0 + 8 * 68 + 4 + (OQL - OQH)];
        }
        float Sf[32];          // 8 nb x 4
        #pragma unroll
        for (int i = 0; i < 32; ++i) Sf[i] = 0.f;
        // S = Q.K^T
        #pragma unroll
        for (int nb = 0; nb < 8; ++nb){
            int base = OKH + (8 * nb + q4) * 68 + h * 16 + t4;
            #pragma unroll
            for (int ks = 0; ks < 2; ++ks){
                u32 Bh[2] = { smw[base + 8*ks], smw[base + 8*ks + 4] };
                u32 Bl[2] = { smw[base + 8*ks + (OKL - OKH)], smw[base + 8*ks + 4 + (OKL - OKH)] };
                mma16816(&Sf[nb*4], &QAh[ks*4], Bh);
                mma16816(&Sf[nb*4], &QAh[ks*4], Bl);
                mma16816(&Sf[nb*4], &QAl[ks*4], Bh);
            }
        }
        // fragment softmax: rows r0 (idx 0,1) and r0+8 (idx 2,3)
        float mx0 = -3.4e38f, mx1 = -3.4e38f;
        #pragma unroll
        for (int nb = 0; nb < 8; ++nb){
            mx0 = fmaxf(mx0, fmaxf(Sf[nb*4],     Sf[nb*4 + 1]));
            mx1 = fmaxf(mx1, fmaxf(Sf[nb*4 + 2], Sf[nb*4 + 3]));
        }
        mx0 = fmaxf(mx0, __shfl_xor_sync(0xffffffffu, mx0, 1));
        mx0 = fmaxf(mx0, __shfl_xor_sync(0xffffffffu, mx0, 2));
        mx1 = fmaxf(mx1, __shfl_xor_sync(0xffffffffu, mx1, 1));
        mx1 = fmaxf(mx1, __shfl_xor_sync(0xffffffffu, mx1, 2));
        float sum0 = 0.f, sum1 = 0.f;
        #pragma unroll
        for (int nb = 0; nb < 8; ++nb){
            Sf[nb*4]     = __expf(Sf[nb*4]     - mx0);
            Sf[nb*4 + 1] = __expf(Sf[nb*4 + 1] - mx0);
            Sf[nb*4 + 2] = __expf(Sf[nb*4 + 2] - mx1);
            Sf[nb*4 + 3] = __expf(Sf[nb*4 + 3] - mx1);
            sum0 += Sf[nb*4] + Sf[nb*4 + 1];
            sum1 += Sf[nb*4 + 2] + Sf[nb*4 + 3];
        }
        sum0 += __shfl_xor_sync(0xffffffffu, sum0, 1);
        sum0 += __shfl_xor_sync(0xffffffffu, sum0, 2);
        sum1 += __shfl_xor_sync(0xffffffffu, sum1, 1);
        sum1 += __shfl_xor_sync(0xffffffffu, sum1, 2);
        float inv0 = 1.0f / sum0, inv1 = 1.0f / sum1;
        // P frags (hi/lo)
        u32 Pa[16], Pl[16];
        #pragma unroll
        for (int k2 = 0; k2 < 4; ++k2){
            float p00 = Sf[(2*k2)*4]     * inv0, p01 = Sf[(2*k2)*4 + 1] * inv0;
            float p10 = Sf[(2*k2)*4 + 2] * inv1, p11 = Sf[(2*k2)*4 + 3] * inv1;
            float p20 = Sf[(2*k2+1)*4]     * inv0, p21 = Sf[(2*k2+1)*4 + 1] * inv0;
            float p30 = Sf[(2*k2+1)*4 + 2] * inv1, p31 = Sf[(2*k2+1)*4 + 3] * inv1;
            u32 h0 = bf2(p00, p01), h1 = bf2(p10, p11);
            u32 h2 = bf2(p20, p21), h3 = bf2(p30, p31);
            Pa[k2*4]     = h0; Pa[k2*4 + 1] = h1;
            Pa[k2*4 + 2] = h2; Pa[k2*4 + 3] = h3;
            Pl[k2*4]     = bf2(p00 - __uint_as_float(h0 << 16), p01 - __uint_as_float(h0 & 0xffff0000u));
            Pl[k2*4 + 1] = bf2(p10 - __uint_as_float(h1 << 16), p11 - __uint_as_float(h1 & 0xffff0000u));
            Pl[k2*4 + 2] = bf2(p20 - __uint_as_float(h2 << 16), p21 - __uint_as_float(h2 & 0xffff0000u));
            Pl[k2*4 + 3] = bf2(p30 - __uint_as_float(h3 << 16), p31 - __uint_as_float(h3 & 0xffff0000u));
        }
        // ctx = P.V
        float C2[16];
        #pragma unroll
        for (int i = 0; i < 16; ++i) C2[i] = 0.f;
        #pragma unroll
        for (int nb2 = 0; nb2 < 4; ++nb2){
            int vbase = OVTH + (h * 32 + 8 * nb2 + q4) * 36 + t4;
            #pragma unroll
            for (int k2 = 0; k2 < 4; ++k2){
                u32 Bh[2] = { smw[vbase + 8*k2], smw[vbase + 8*k2 + 4] };
                u32 Bl[2] = { smw[vbase + 8*k2 + (OVTL - OVTH)], smw[vbase + 8*k2 + 4 + (OVTL - OVTH)] };
                mma16816(&C2[nb2*4], &Pa[k2*4], Bh);
                mma16816(&C2[nb2*4], &Pa[k2*4], Bl);
                mma16816(&C2[nb2*4], &Pl[k2*4], Bh);
            }
        }
        // ctx writeback as bf16 hi/lo A-layout
        #pragma unroll
        for (int nb2 = 0; nb2 < 4; ++nb2){
            int w = h * 16 + 4 * nb2 + t4;
            u32 h0 = bf2(C2[nb2*4],     C2[nb2*4 + 1]);
            u32 h1 = bf2(C2[nb2*4 + 2], C2[nb2*4 + 3]);
            smw[OCXH + r0 * 68 + w]       = h0;
            smw[OCXH + (r0 + 8) * 68 + w] = h1;
            smw[OCXL + r0 * 68 + w] =
                bf2(C2[nb2*4]     - __uint_as_float(h0 << 16),
                    C2[nb2*4 + 1] - __uint_as_float(h0 & 0xffff0000u));
            smw[OCXL + (r0 + 8) * 68 + w] =
                bf2(C2[nb2*4 + 2] - __uint_as_float(h1 << 16),
                    C2[nb2*4 + 3] - __uint_as_float(h1 & 0xffff0000u));
        }
    }
    CPWAIT(0);
    __syncthreads();   // ctx visible; Q dead -> QA region reusable

    // ---------------- out-proj: ctx(bf16) @ W_out^T + b_out -> QA ----------------
    {
        #pragma unroll
        for (int ks = 0; ks < 8; ++ks){
            int a0 = OCXH + (s16 + q4) * 68 + 8 * ks + t4;
            Ah[ks*4]     = smw[a0];
            Ah[ks*4 + 1] = smw[a0 + 8 * 68];
            Ah[ks*4 + 2] = smw[a0 + 4];
            Ah[ks*4 + 3] = smw[a0 + 8 * 68 + 4];
            Al[ks*4]     = smw[a0 + (OCXL - OCXH)];
            Al[ks*4 + 1] = smw[a0 + 8 * 68 + (OCXL - OCXH)];
            Al[ks*4 + 2] = smw[a0 + 4 + (OCXL - OCXH)];
            Al[ks*4 + 3] = smw[a0 + 8 * 68 + 4 + (OCXL - OCXH)];
        }
        for (int si = 0; si < 2; ++si){
            const u32 bufw = si ? OWSB : OWSA;
            for (int j = 0; j < 2; ++j){
                float acc[4] = {0.f, 0.f, 0.f, 0.f};
                int bw = bufw + (u32)(nq * 16 + 8 * j + q4) * 68 + t4;
                #pragma unroll
                for (int p = 0; p < 4; ++p){
                    u32 Bh[4], Bl[4];
                    int bp = bw + p * 16;
                    Bh[0] = smw[bp];      Bh[1] = smw[bp + 4];
                    Bh[2] = smw[bp + 8];  Bh[3] = smw[bp + 12];
                    Bl[0] = smw[bp + WLO];      Bl[1] = smw[bp + 4 + WLO];
                    Bl[2] = smw[bp + 8 + WLO];  Bl[3] = smw[bp + 12 + WLO];
                    mma16816(acc, &Ah[8*p],     &Bh[0]);
                    mma16816(acc, &Ah[8*p],     &Bl[0]);
                    mma16816(acc, &Al[8*p],     &Bh[0]);
                    mma16816(acc, &Ah[8*p + 4], &Bh[2]);
                    mma16816(acc, &Ah[8*p + 4], &Bl[2]);
                    mma16816(acc, &Al[8*p + 4], &Bh[2]);
                }
                int e0 = si * 64 + nq * 16 + 8 * j + 2 * t4;
                int r0 = s16 + q4;
                sm[OQA + r0 * 128 + e0]           = acc[0] + b_out[e0];
                sm[OQA + r0 * 128 + e0 + 1]       = acc[1] + b_out[e0 + 1];
                sm[OQA + (r0 + 8) * 128 + e0]     = acc[2] + b_out[e0];
                sm[OQA + (r0 + 8) * 128 + e0 + 1] = acc[3] + b_out[e0 + 1];
            }
        }
    }
    __syncthreads();

    // ---------------- pooling + projections ----------------
    #pragma unroll
    for (int i = 0; i < 4; ++i) {
        int l = warp * 4 + i;
        float p = 0.f;
        #pragma unroll
        for (int c = 0; c < 4; ++c) {
            int d = lane + 32 * c;
            p = fmaf(sm[OQA + l * 128 + d], xg[l * 128 + d], p);
        }
        #pragma unroll
        for (int o = 16; o > 0; o >>= 1) p += __shfl_xor_sync(0xffffffffu, p, o);
        if (lane == 0) sm[OAW + l] = p;
    }
    __syncthreads();
    if (warp == 0) {
        float va = sm[OAW + lane], vb = sm[OAW + lane + 32];
        float mx = fmaxf(va, vb);
        #pragma unroll
        for (int o = 16; o > 0; o >>= 1)
            mx = fmaxf(mx, __shfl_xor_sync(0xffffffffu, mx, o));
        float ea = __expf(va - mx), eb = __expf(vb - mx);
        float s = ea + eb;
        #pragma unroll
        for (int o = 16; o > 0; o >>= 1) s += __shfl_xor_sync(0xffffffffu, s, o);
        float inv = 1.0f / s;
        sm[OAW + lane]      = ea * inv;
        sm[OAW + lane + 32] = eb * inv;
    }
    __syncthreads();
    if (tid < 128) {
        int d = tid;
        float wacc = 0.f, s = 0.f, s2 = 0.f, mx = -3.4e38f;
        #pragma unroll 8
        for (int l = 0; l < 64; ++l) {
            float a = sm[OQA + l * 128 + d];
            wacc = fmaf(sm[OAW + l], a, wacc);
            s += a;
            s2 = fmaf(a, a, s2);
            mx = fmaxf(mx, a);
        }
        float mean = s * (1.0f / 64.0f);
        float var  = (s2 - s * mean) * (1.0f / 63.0f);
        sm[OPOOL + d]       = wacc;
        sm[OPOOL + 128 + d] = mx;
        sm[OPOOL + 256 + d] = mean;
        sm[OPOOL + 384 + d] = sqrtf(fmaxf(var, 0.0f));
    }
    __syncthreads();
    {
        int p  = warp >> 2;            // 0..3 pool slot
        int f0 = (warp & 3) * 4;       // 4 outputs per warp
        #pragma unroll
        for (int fi = 0; fi < 4; ++fi) {
            int o = p * 16 + f0 + fi;
            float acc = 0.f;
            #pragma unroll
            for (int c = 0; c < 4; ++c) {
                int d = lane + 32 * c;
                acc = fmaf(sm[OPOOL + p * 128 + d], W_pool[(size_t)o * 128 + d], acc);
            }
            #pragma unroll
            for (int off = 16; off > 0; off >>= 1)
                acc += __shfl_xor_sync(0xffffffffu, acc, off);
            if (lane == 0) out[(size_t)bm * 64 + o] = acc + b_pool[o];
        }
    }
}

extern "C" void kernel_launch(void* const* d_in, const int* in_sizes, int n_in,
                              void* d_out, int out_size)
{
    const float* x      = (const float*)d_in[0];
    const float* W_in   = (const float*)d_in[2];
    const float* b_in   = (const float*)d_in[3];
    const float* W_out  = (const float*)d_in[4];
    const float* b_out  = (const float*)d_in[5];
    const float* W_pool = (const float*)d_in[6];
    const float* b_pool = (const float*)d_in[7];
    float* out = (float*)d_out;

    int nmol = in_sizes[0] / (64 * 128);   // 8192

    prep_kernel<<<256, 256>>>(W_in, W_out);
    cudaFuncSetAttribute(feat_kernel,
                         cudaFuncAttributeMaxDynamicSharedMemorySize, SMEM_BYTES);
    feat_kernel<<<nmol, NT, SMEM_BYTES>>>(x, b_in, b_out,
                                          W_pool, b_pool, out);
}